// round 4
// baseline (speedup 1.0000x reference)
#include <cuda_runtime.h>
#include <math.h>

#define NB 4
#define NC 128
#define NN 4096
#define NK 9

// ---------------- device scratch ----------------
__device__ __align__(16) float d_WT[128 * 384];     // [c][o] combined weights (P|Q|AW|pad)
__device__ float d_bias[384];
__device__ float d_xx[NB * NN];
__device__ int   d_knn_buf[NB * NN * NK];
__device__ __align__(16) float d_PQA[NB * NN * 384]; // [b][n][o]
__device__ __align__(16) float d_Y[NB * NN * 128];   // [b][n][c]
__device__ __align__(16) float d_Z[NB * 128 * NN];   // [b][o][n]
__device__ float d_gnp_s[16 * NN];
__device__ float d_gnp_q[16 * NN];
__device__ float d_gnm[16], d_gni[16];
__device__ __align__(16) float d_WPT[NB * 128 * 128]; // [b][c][o]
__device__ float d_E[NB * 128];
__device__ float d_bnp_s[128 * 128], d_bnp_q[128 * 128];
__device__ float d_bnm[128], d_bni[128];

// ---------------- f32x2 helpers ----------------
__device__ __forceinline__ unsigned long long pack2(float x, float y) {
    unsigned long long r;
    asm("mov.b64 %0, {%1, %2};" : "=l"(r) : "f"(x), "f"(y));
    return r;
}
__device__ __forceinline__ void fma2(unsigned long long& d, unsigned long long a, unsigned long long b) {
    asm("fma.rn.f32x2 %0, %1, %2, %0;" : "+l"(d) : "l"(a), "l"(b));
}
__device__ __forceinline__ float2 unpk(unsigned long long v) {
    float2 r;
    asm("mov.b64 {%0, %1}, %2;" : "=f"(r.x), "=f"(r.y) : "l"(v));
    return r;
}

// key: descending by value, ties -> smaller index first (matches lax.top_k)
__device__ __forceinline__ unsigned long long enckey(float v, int m) {
    unsigned u = __float_as_uint(v);
    unsigned mask = ((int)u < 0) ? 0xFFFFFFFFu : 0x80000000u;
    u ^= mask;
    return ((unsigned long long)u << 32) | (unsigned)(~m);
}
__device__ __forceinline__ void insert9(unsigned long long* bk, unsigned long long key) {
    if (key <= bk[8]) return;
    #pragma unroll
    for (int q = 0; q < 9; q++) {
        if (key > bk[q]) { unsigned long long t = bk[q]; bk[q] = key; key = t; }
    }
}

// ---------------- k0: combined weights (transposed) ----------------
__global__ void prep_kernel(const float* __restrict__ w_lin, const float* __restrict__ b_lin,
                            const float* __restrict__ w_aw, const float* __restrict__ b_aw) {
    int i = blockIdx.x * 256 + threadIdx.x;
    if (i >= 384 * 128) return;
    int o = i % 384, c = i / 384;
    float w = 0.f;
    if (o < 128)      w = w_lin[o * 256 + c] + w_lin[o * 256 + 128 + c];
    else if (o < 256) w = w_lin[(o - 128) * 256 + 128 + c];
    else if (o < 292) w = w_aw[(o - 256) * 128 + c];
    d_WT[c * 384 + o] = w;
    if (c == 0) {
        float bv = 0.f;
        if (o < 128) bv = b_lin[o];
        else if (o >= 256 && o < 292) bv = b_aw[o - 256];
        d_bias[o] = bv;
    }
}

// ---------------- k1: xx ----------------
__global__ void xx_kernel(const float* __restrict__ x) {
    int i = blockIdx.x * 256 + threadIdx.x;
    int b = i >> 12, n = i & (NN - 1);
    float s = 0.f;
    #pragma unroll 8
    for (int c = 0; c < 128; c++) {
        float v = x[(b * 128 + c) * NN + n];
        s = fmaf(v, v, s);
    }
    d_xx[i] = s;
}

// ---------------- k2: KNN ----------------
// block: 32 query rows; 256 threads; thread = (tr=tid/16 -> 2 rows, tm=tid%16 -> 8 m)
__global__ void __launch_bounds__(256) knn_kernel(const float* __restrict__ x) {
    const int b = blockIdx.y;
    const int n0 = blockIdx.x * 32;
    const int tid = threadIdx.x;
    __shared__ __align__(16) unsigned long long pool[32 * 145];
    float* xnT = (float*)pool;              // [128][36]
    float* xmB = xnT + 128 * 36;            // 2 x [16][132]

    for (int i = tid; i < 128 * 32; i += 256) {
        int c = i >> 5, r = i & 31;
        xnT[c * 36 + r] = x[(b * 128 + c) * NN + n0 + r];
    }
    const int tr = tid >> 4;
    const int tm = tid & 15;
    const int r0 = tr * 2;

    unsigned long long bk0[9], bk1[9];
    #pragma unroll
    for (int q = 0; q < 9; q++) { bk0[q] = 0ull; bk1[q] = 0ull; }

    for (int mt = 0; mt < 32; mt++) {
        const int m0 = mt * 128;
        unsigned long long a00 = 0, a01 = 0, a02 = 0, a03 = 0;
        unsigned long long a10 = 0, a11 = 0, a12 = 0, a13 = 0;

        // preload chunk 0
        {
            #pragma unroll
            for (int u = 0; u < 8; u++) {
                int i5 = tid + u * 256;
                int cc5 = i5 >> 7, m5 = i5 & 127;
                xmB[cc5 * 132 + m5] = x[(b * 128 + cc5) * NN + m0 + m5];
            }
        }
        __syncthreads();

        for (int ck = 0; ck < 8; ck++) {
            float tmp[8];
            if (ck < 7) {
                #pragma unroll
                for (int u = 0; u < 8; u++) {
                    int i5 = tid + u * 256;
                    int cc5 = i5 >> 7, m5 = i5 & 127;
                    tmp[u] = x[(b * 128 + (ck + 1) * 16 + cc5) * NN + m0 + m5];
                }
            }
            const float* xb = xmB + (ck & 1) * 2112;
            #pragma unroll
            for (int cc = 0; cc < 16; cc++) {
                const float* xr = xnT + (ck * 16 + cc) * 36 + r0;
                float av0 = xr[0], av1 = xr[1];
                ulonglong2 b01 = *(const ulonglong2*)(const void*)(xb + cc * 132 + tm * 8);
                ulonglong2 b23 = *(const ulonglong2*)(const void*)(xb + cc * 132 + tm * 8 + 4);
                unsigned long long ad = pack2(av0, av0);
                fma2(a00, ad, b01.x); fma2(a01, ad, b01.y);
                fma2(a02, ad, b23.x); fma2(a03, ad, b23.y);
                ad = pack2(av1, av1);
                fma2(a10, ad, b01.x); fma2(a11, ad, b01.y);
                fma2(a12, ad, b23.x); fma2(a13, ad, b23.y);
            }
            if (ck < 7) {
                float* dst = xmB + ((ck + 1) & 1) * 2112;
                #pragma unroll
                for (int u = 0; u < 8; u++) {
                    int i5 = tid + u * 256;
                    dst[(i5 >> 7) * 132 + (i5 & 127)] = tmp[u];
                }
            }
            __syncthreads();
        }

        // selection
        float2 p0 = unpk(a00), p1 = unpk(a01), p2 = unpk(a02), p3 = unpk(a03);
        float v0[8] = {p0.x, p0.y, p1.x, p1.y, p2.x, p2.y, p3.x, p3.y};
        p0 = unpk(a10); p1 = unpk(a11); p2 = unpk(a12); p3 = unpk(a13);
        float v1[8] = {p0.x, p0.y, p1.x, p1.y, p2.x, p2.y, p3.x, p3.y};
        #pragma unroll
        for (int jj = 0; jj < 8; jj++) {
            int m = m0 + tm * 8 + jj;
            float xxm = d_xx[b * NN + m];
            insert9(bk0, enckey(2.f * v0[jj] - xxm, m));
            insert9(bk1, enckey(2.f * v1[jj] - xxm, m));
        }
    }

    // merge 16 sorted lists per row
    __syncthreads();
    #pragma unroll
    for (int q = 0; q < 9; q++) {
        pool[(r0 + 0) * 145 + tm * 9 + q] = bk0[q];
        pool[(r0 + 1) * 145 + tm * 9 + q] = bk1[q];
    }
    __syncthreads();
    if (tid < 32) {
        int rl = tid;
        int h[16];
        #pragma unroll
        for (int l = 0; l < 16; l++) h[l] = 0;
        const unsigned long long* row = pool + rl * 145;
        for (int q = 0; q < 9; q++) {
            unsigned long long best = 0; int bl = 0;
            #pragma unroll
            for (int l = 0; l < 16; l++) {
                if (h[l] < 9) {
                    unsigned long long kk = row[l * 9 + h[l]];
                    if (kk > best) { best = kk; bl = l; }
                }
            }
            h[bl]++;
            d_knn_buf[(b * NN + n0 + rl) * NK + q] = (int)(~(unsigned)best);
        }
    }
}

// ---------------- k3: GEMM A  out[b][n][o] = sum_c WT[c][o]*x[b][c][n] + bias ----------------
__global__ void __launch_bounds__(256) gemmA_kernel(const float* __restrict__ x) {
    int b = blockIdx.y, n0 = blockIdx.x * 128, o0 = blockIdx.z * 128;
    __shared__ __align__(16) float Ws[32 * 132];
    __shared__ __align__(16) float Xs[32 * 132];
    int tx = threadIdx.x & 15, ty = threadIdx.x >> 4;
    float acc[8][8];
    {
        float bias[8];
        #pragma unroll
        for (int i = 0; i < 8; i++) bias[i] = d_bias[o0 + ty * 8 + i];
        #pragma unroll
        for (int j = 0; j < 8; j++)
            #pragma unroll
            for (int i = 0; i < 8; i++) acc[j][i] = bias[i];
    }
    for (int c0 = 0; c0 < 128; c0 += 32) {
        __syncthreads();
        for (int t = threadIdx.x; t < 32 * 128; t += 256) {
            int cc = t >> 7, oo = t & 127;
            Ws[cc * 132 + oo] = d_WT[(c0 + cc) * 384 + o0 + oo];
            Xs[cc * 132 + oo] = x[(b * 128 + c0 + cc) * NN + n0 + oo];
        }
        __syncthreads();
        #pragma unroll
        for (int cc = 0; cc < 32; cc++) {
            float4 w0 = *(const float4*)(Ws + cc * 132 + ty * 8);
            float4 w1 = *(const float4*)(Ws + cc * 132 + ty * 8 + 4);
            #pragma unroll
            for (int j = 0; j < 8; j++) {
                float xv = Xs[cc * 132 + tx + 16 * j];
                acc[j][0] = fmaf(w0.x, xv, acc[j][0]);
                acc[j][1] = fmaf(w0.y, xv, acc[j][1]);
                acc[j][2] = fmaf(w0.z, xv, acc[j][2]);
                acc[j][3] = fmaf(w0.w, xv, acc[j][3]);
                acc[j][4] = fmaf(w1.x, xv, acc[j][4]);
                acc[j][5] = fmaf(w1.y, xv, acc[j][5]);
                acc[j][6] = fmaf(w1.z, xv, acc[j][6]);
                acc[j][7] = fmaf(w1.w, xv, acc[j][7]);
            }
        }
    }
    #pragma unroll
    for (int j = 0; j < 8; j++) {
        int n = n0 + tx + 16 * j;
        float* dp = d_PQA + (b * NN + n) * 384 + o0 + ty * 8;
        *(float4*)dp       = make_float4(acc[j][0], acc[j][1], acc[j][2], acc[j][3]);
        *(float4*)(dp + 4) = make_float4(acc[j][4], acc[j][5], acc[j][6], acc[j][7]);
    }
}

// ---------------- k4: per-point attention ----------------
__global__ void __launch_bounds__(128) attn_kernel(const float* __restrict__ x) {
    int n = blockIdx.x, b = blockIdx.y;
    int c = threadIdx.x, g = c >> 5;
    __shared__ float fS[9 * 132];
    __shared__ float sS[4 * 81];
    __shared__ float awS[36], tS[36];
    __shared__ int idxS[9];
    int base = (b * NN + n) * 384;
    if (c < 9)  idxS[c] = d_knn_buf[(b * NN + n) * NK + c];
    if (c < 36) awS[c] = d_PQA[base + 256 + c];
    __syncthreads();
    float P = d_PQA[base + c];
    float e9[9];
    #pragma unroll
    for (int k = 0; k < 9; k++) {
        float f = P - d_PQA[(b * NN + idxS[k]) * 384 + 128 + c];
        fS[k * 132 + c] = f;
        e9[k] = f > 0.f ? f : expm1f(f);
    }
    if (c < 4) {
        float* row = awS + c * 9;
        float mx = row[0];
        #pragma unroll
        for (int k = 1; k < 9; k++) mx = fmaxf(mx, row[k]);
        float sm = 0.f;
        #pragma unroll
        for (int k = 0; k < 9; k++) { float e = expf(row[k] - mx); row[k] = e; sm += e; }
        float inv = 1.f / sm;
        #pragma unroll
        for (int k = 0; k < 9; k++) row[k] *= inv;
    }
    __syncthreads();
    for (int t = c; t < 324; t += 128) {
        int g2 = t / 81, p = t % 81, k = p / 9, j = p % 9;
        const float* fa = fS + k * 132 + g2 * 32;
        const float* fb = fS + j * 132 + g2 * 32;
        float s = 0.f;
        #pragma unroll
        for (int q = 0; q < 32; q++) s = fmaf(fa[q], fb[q], s);
        sS[g2 * 81 + p] = s * 0.17677669529663689f;
    }
    __syncthreads();
    if (c < 36) {
        float* row = sS + (c / 9) * 81 + (c % 9) * 9;
        float mx = row[0];
        #pragma unroll
        for (int j = 1; j < 9; j++) mx = fmaxf(mx, row[j]);
        float sm = 0.f;
        #pragma unroll
        for (int j = 0; j < 9; j++) { float e = expf(row[j] - mx); row[j] = e; sm += e; }
        float inv = 1.f / sm;
        #pragma unroll
        for (int j = 0; j < 9; j++) row[j] *= inv;
    }
    __syncthreads();
    if (c < 36) {
        int g2 = c / 9, j = c % 9;
        float tv = 0.f;
        #pragma unroll
        for (int k = 0; k < 9; k++) tv = fmaf(awS[g2 * 9 + k], sS[g2 * 81 + k * 9 + j], tv);
        tS[c] = tv;
    }
    __syncthreads();
    float lf = 0.f;
    #pragma unroll
    for (int j = 0; j < 9; j++) lf = fmaf(tS[g * 9 + j], e9[j], lf);
    float yv = lf + x[(b * 128 + c) * NN + n];
    d_Y[(b * NN + n) * 128 + c] = yv;
    float s1 = yv, s2 = yv * yv;
    #pragma unroll
    for (int off = 16; off; off >>= 1) {
        s1 += __shfl_xor_sync(0xffffffffu, s1, off);
        s2 += __shfl_xor_sync(0xffffffffu, s2, off);
    }
    if ((c & 31) == 0) {
        d_gnp_s[(b * 4 + g) * NN + n] = s1;
        d_gnp_q[(b * 4 + g) * NN + n] = s2;
    }
}

// ---------------- k5: GN stats (deterministic) ----------------
__global__ void gn_stats_kernel() {
    int bg = blockIdx.x;
    __shared__ double sh[256], sh2[256];
    double s = 0.0, q = 0.0;
    for (int i = threadIdx.x; i < NN; i += 256) {
        s += (double)d_gnp_s[bg * NN + i];
        q += (double)d_gnp_q[bg * NN + i];
    }
    sh[threadIdx.x] = s; sh2[threadIdx.x] = q;
    __syncthreads();
    for (int off = 128; off; off >>= 1) {
        if (threadIdx.x < off) { sh[threadIdx.x] += sh[threadIdx.x + off]; sh2[threadIdx.x] += sh2[threadIdx.x + off]; }
        __syncthreads();
    }
    if (threadIdx.x == 0) {
        double cnt = 32.0 * NN;
        double mean = sh[0] / cnt;
        double var = sh2[0] / cnt - mean * mean;
        d_gnm[bg] = (float)mean;
        d_gni[bg] = (float)(1.0 / sqrt(var + 1e-5));
    }
}

// ---------------- k6: fold GN into conv weights ----------------
__global__ void prepw_kernel(const float* __restrict__ conv_w, const float* __restrict__ conv_b,
                             const float* __restrict__ gn_g, const float* __restrict__ gn_b) {
    int b = blockIdx.x, o = threadIdx.x;
    float e = conv_b[o];
    for (int c = 0; c < 128; c++) {
        int g = c >> 5;
        float inv = d_gni[b * 4 + g];
        float A = gn_g[c] * inv;
        float D = gn_b[c] - d_gnm[b * 4 + g] * A;
        float w = conv_w[o * 128 + c];
        e = fmaf(w, D, e);
        d_WPT[(b * 128 + c) * 128 + o] = w * A;
    }
    d_E[b * 128 + o] = e;
}

// ---------------- k7: GEMM B  z[b][o][n] = sum_c WPT[b][c][o]*Y[b][n][c] + E ----------------
__global__ void __launch_bounds__(256) gemmB_kernel() {
    int b = blockIdx.y, n0 = blockIdx.x * 128;
    __shared__ __align__(16) float Ws[32 * 132];
    __shared__ __align__(16) float Ys[128 * 33];
    int tx = threadIdx.x & 15, ty = threadIdx.x >> 4;
    float acc[8][8];
    {
        float eb[8];
        #pragma unroll
        for (int i = 0; i < 8; i++) eb[i] = d_E[b * 128 + ty * 8 + i];
        #pragma unroll
        for (int j = 0; j < 8; j++)
            #pragma unroll
            for (int i = 0; i < 8; i++) acc[j][i] = eb[i];
    }
    for (int c0 = 0; c0 < 128; c0 += 32) {
        __syncthreads();
        for (int t = threadIdx.x; t < 32 * 128; t += 256) {
            int cc = t >> 7, oo = t & 127;
            Ws[cc * 132 + oo] = d_WPT[(b * 128 + c0 + cc) * 128 + oo];
            int nl = t >> 5, cl = t & 31;
            Ys[nl * 33 + cl] = d_Y[(b * NN + n0 + nl) * 128 + c0 + cl];
        }
        __syncthreads();
        #pragma unroll
        for (int cc = 0; cc < 32; cc++) {
            float4 w0 = *(const float4*)(Ws + cc * 132 + ty * 8);
            float4 w1 = *(const float4*)(Ws + cc * 132 + ty * 8 + 4);
            #pragma unroll
            for (int j = 0; j < 8; j++) {
                float yv = Ys[(tx + 16 * j) * 33 + cc];
                acc[j][0] = fmaf(w0.x, yv, acc[j][0]);
                acc[j][1] = fmaf(w0.y, yv, acc[j][1]);
                acc[j][2] = fmaf(w0.z, yv, acc[j][2]);
                acc[j][3] = fmaf(w0.w, yv, acc[j][3]);
                acc[j][4] = fmaf(w1.x, yv, acc[j][4]);
                acc[j][5] = fmaf(w1.y, yv, acc[j][5]);
                acc[j][6] = fmaf(w1.z, yv, acc[j][6]);
                acc[j][7] = fmaf(w1.w, yv, acc[j][7]);
            }
        }
    }
    #pragma unroll
    for (int j = 0; j < 8; j++) {
        int n = n0 + tx + 16 * j;
        #pragma unroll
        for (int i = 0; i < 8; i++)
            d_Z[(b * 128 + ty * 8 + i) * NN + n] = acc[j][i];
    }
    // deterministic per-block BN partials
    float* red = Ys;
    __syncthreads();
    #pragma unroll
    for (int i = 0; i < 8; i++) {
        float s = 0.f, q = 0.f;
        #pragma unroll
        for (int j = 0; j < 8; j++) { s += acc[j][i]; q = fmaf(acc[j][i], acc[j][i], q); }
        red[(ty * 8 + i) * 16 + tx] = s;
        red[2048 + (ty * 8 + i) * 16 + tx] = q;
    }
    __syncthreads();
    if (threadIdx.x < 128) {
        int o = threadIdx.x;
        float s = 0.f, q = 0.f;
        #pragma unroll
        for (int t = 0; t < 16; t++) { s += red[o * 16 + t]; q += red[2048 + o * 16 + t]; }
        int blk = blockIdx.y * 32 + blockIdx.x;
        d_bnp_s[o * 128 + blk] = s;
        d_bnp_q[o * 128 + blk] = q;
    }
}

// ---------------- k8: BN stats ----------------
__global__ void bn_stats_kernel() {
    int o = threadIdx.x;
    double s = 0.0, q = 0.0;
    for (int k = 0; k < 128; k++) { s += (double)d_bnp_s[o * 128 + k]; q += (double)d_bnp_q[o * 128 + k]; }
    double cnt = (double)(NB * NN);
    double mean = s / cnt;
    double var = q / cnt - mean * mean;
    d_bnm[o] = (float)mean;
    d_bni[o] = (float)(1.0 / sqrt(var + 1e-5));
}

// ---------------- k9: BN apply + relu ----------------
__global__ void final_kernel(const float* __restrict__ bn_g, const float* __restrict__ bn_b,
                             float* __restrict__ out) {
    int i = blockIdx.x * 256 + threadIdx.x;
    int o = (i >> 12) & 127;
    float v = (d_Z[i] - d_bnm[o]) * d_bni[o] * bn_g[o] + bn_b[o];
    out[i] = fmaxf(v, 0.f);
}

extern "C" void kernel_launch(void* const* d_in, const int* in_sizes, int n_in,
                              void* d_out, int out_size) {
    const float* x      = (const float*)d_in[0];
    const float* w_lin  = (const float*)d_in[1];
    const float* b_lin  = (const float*)d_in[2];
    const float* w_aw   = (const float*)d_in[3];
    const float* b_aw   = (const float*)d_in[4];
    const float* gn_g   = (const float*)d_in[5];
    const float* gn_b   = (const float*)d_in[6];
    const float* conv_w = (const float*)d_in[7];
    const float* conv_b = (const float*)d_in[8];
    const float* bn_g   = (const float*)d_in[9];
    const float* bn_b   = (const float*)d_in[10];
    float* out = (float*)d_out;

    prep_kernel<<<192, 256>>>(w_lin, b_lin, w_aw, b_aw);
    xx_kernel<<<64, 256>>>(x);
    knn_kernel<<<dim3(128, 4), 256>>>(x);
    gemmA_kernel<<<dim3(32, 4, 3), 256>>>(x);
    attn_kernel<<<dim3(4096, 4), 128>>>(x);
    gn_stats_kernel<<<16, 256>>>();
    prepw_kernel<<<4, 128>>>(conv_w, conv_b, gn_g, gn_b);
    gemmB_kernel<<<dim3(32, 4), 256>>>();
    bn_stats_kernel<<<1, 128>>>();
    final_kernel<<<8192, 256>>>(bn_g, bn_b, out);
}